// round 1
// baseline (speedup 1.0000x reference)
#include <cuda_runtime.h>

#define B_        128
#define QN        16
#define LN        2048
#define EMB_      128
#define KN        11
#define TPB       256
#define SPLIT     2
#define DOCS_PER_CTA   (LN / SPLIT)        // 1024
#define DOCS_PER_PASS  512
#define NPASS          (DOCS_PER_CTA / DOCS_PER_PASS)  // 2
#define SIMSTR    17                        // padded stride to dodge bank conflicts

// Scratch for cross-CTA pooled accumulation (no cudaMalloc allowed).
__device__ float g_pooled[B_ * QN * KN];

__constant__ float c_mu[KN] = {
    -1.0f, -0.8f, -0.6f, -0.4f, -0.2f, 0.0f, 0.2f, 0.4f, 0.6f, 0.8f, 1.0f
};

// ---- packed fp32 helpers (sm_103a f32x2 pipe: 2x FFMA throughput) ----
__device__ __forceinline__ void fma2(unsigned long long& d,
                                     unsigned long long a,
                                     unsigned long long b) {
    asm("fma.rn.f32x2 %0, %1, %2, %0;" : "+l"(d) : "l"(a), "l"(b));
}
__device__ __forceinline__ float2 up2(unsigned long long v) {
    float2 r;
    asm("mov.b64 {%0, %1}, %2;" : "=f"(r.x), "=f"(r.y) : "l"(v));
    return r;
}

extern "C" __global__ void __launch_bounds__(TPB, 2)
knrm_main(const int* __restrict__ queries,
          const int* __restrict__ docs,
          const float* __restrict__ emb)
{
    __shared__ __align__(16) float qs[QN * EMB_];                 // 8 KB, normalized queries
    __shared__ __align__(16) float sims[DOCS_PER_PASS * SIMSTR];  // 34 KB sim buffer (aliased as 'red' later)

    const int b     = blockIdx.y;
    const int chunk = blockIdx.x;
    const int tid   = threadIdx.x;

    // ---------- Stage 1: gather + normalize queries into smem ----------
    {
        int q    = tid >> 4;        // 16 threads per query row
        int part = tid & 15;        // each handles 8 floats
        int qi   = queries[b * QN + q];
        const float4* qr = (const float4*)(emb + (size_t)qi * EMB_);
        float4 v0 = __ldg(&qr[part * 2]);
        float4 v1 = __ldg(&qr[part * 2 + 1]);
        float ss = v0.x*v0.x + v0.y*v0.y + v0.z*v0.z + v0.w*v0.w
                 + v1.x*v1.x + v1.y*v1.y + v1.z*v1.z + v1.w*v1.w;
        #pragma unroll
        for (int o = 8; o; o >>= 1)
            ss += __shfl_xor_sync(0xffffffffu, ss, o, 16);
        float rn = (ss > 0.0f) ? rsqrtf(ss) : 0.0f;  // padding row -> 0 -> sim = 0 (matches eps behavior)
        v0.x *= rn; v0.y *= rn; v0.z *= rn; v0.w *= rn;
        v1.x *= rn; v1.y *= rn; v1.z *= rn; v1.w *= rn;
        float4* dst = (float4*)(qs + q * EMB_ + part * 8);
        dst[0] = v0;
        dst[1] = v1;
    }
    __syncthreads();

    float pk[KN];
    #pragma unroll
    for (int k = 0; k < KN; k++) pk[k] = 0.0f;

    const ulonglong2* qsv = (const ulonglong2*)qs;

    for (int pass = 0; pass < NPASS; ++pass) {
        // ---------- Stage 2: dot products, 2 docs per thread ----------
        const int l0 = chunk * DOCS_PER_CTA + pass * DOCS_PER_PASS;
        const int g0 = docs[b * LN + l0 + tid];
        const int g1 = docs[b * LN + l0 + tid + TPB];
        const ulonglong2* r0 = (const ulonglong2*)(emb + (size_t)g0 * EMB_);
        const ulonglong2* r1 = (const ulonglong2*)(emb + (size_t)g1 * EMB_);

        unsigned long long acc0[QN], acc1[QN], ss0, ss1;
        #pragma unroll
        for (int q = 0; q < QN; q++) { acc0[q] = 0ull; acc1[q] = 0ull; }
        ss0 = 0ull; ss1 = 0ull;

        #pragma unroll 4
        for (int e = 0; e < EMB_ / 4; ++e) {
            ulonglong2 a = __ldg(&r0[e]);  // 4 fp32 of doc0 as 2 packed pairs
            ulonglong2 c = __ldg(&r1[e]);
            fma2(ss0, a.x, a.x); fma2(ss0, a.y, a.y);
            fma2(ss1, c.x, c.x); fma2(ss1, c.y, c.y);
            #pragma unroll
            for (int q = 0; q < QN; q++) {
                ulonglong2 qv = qsv[q * (EMB_ / 4) + e];  // full-CTA smem broadcast
                fma2(acc0[q], a.x, qv.x); fma2(acc0[q], a.y, qv.y);
                fma2(acc1[q], c.x, qv.x); fma2(acc1[q], c.y, qv.y);
            }
        }

        float2 s0 = up2(ss0); float n0 = s0.x + s0.y;
        float2 s1 = up2(ss1); float n1 = s1.x + s1.y;
        float rd0 = (n0 > 0.0f) ? rsqrtf(n0) : 0.0f;
        float rd1 = (n1 > 0.0f) ? rsqrtf(n1) : 0.0f;

        __syncthreads();  // previous pass's RBF readers are done with sims

        #pragma unroll
        for (int q = 0; q < QN; q++) {
            float2 p0 = up2(acc0[q]);
            float2 p1 = up2(acc1[q]);
            sims[tid * SIMSTR + q]         = (p0.x + p0.y) * rd0;
            sims[(tid + TPB) * SIMSTR + q] = (p1.x + p1.y) * rd1;
        }
        __syncthreads();

        // ---------- Stage 3: RBF pooling (MUFU EX2) ----------
        {
            int q   = tid >> 4;
            int sub = tid & 15;
            #pragma unroll 4
            for (int j = 0; j < DOCS_PER_PASS / 16; ++j) {
                float s = sims[(sub + j * 16) * SIMSTR + q];
                #pragma unroll
                for (int k = 0; k < KN; k++) {
                    float t = s - c_mu[k];
                    pk[k] += __expf(t * t * (-50.0f));  // exp(-(s-mu)^2 / (2*0.1^2))
                }
            }
        }
    }
    __syncthreads();

    // ---------- Stage 4: intra-CTA reduce + global atomic merge ----------
    {
        int q   = tid >> 4;
        int sub = tid & 15;
        float* red = sims;  // alias; sims no longer needed
        #pragma unroll
        for (int k = 0; k < KN; k++)
            red[(q * 16 + sub) * KN + k] = pk[k];
        __syncthreads();
        if (tid < QN * KN) {
            int q2 = tid / KN;
            int k2 = tid - q2 * KN;
            float sum = 0.0f;
            #pragma unroll
            for (int s2 = 0; s2 < 16; s2++)
                sum += red[(q2 * 16 + s2) * KN + k2];
            atomicAdd(&g_pooled[(b * QN + q2) * KN + k2], sum);
        }
    }
}

extern "C" __global__ void knrm_zero()
{
    int i = blockIdx.x * blockDim.x + threadIdx.x;
    if (i < B_ * QN * KN) g_pooled[i] = 0.0f;
}

extern "C" __global__ void knrm_epilogue(const float* __restrict__ W,
                                         const float* __restrict__ bias,
                                         float* __restrict__ out)
{
    __shared__ float sh[256];
    int b = blockIdx.x;
    int t = threadIdx.x;
    float v = 0.0f;
    if (t < QN * KN) {
        int q = t / KN;
        int k = t - q * KN;
        v = W[k] * logf(g_pooled[(b * QN + q) * KN + k]);
    }
    sh[t] = v;
    __syncthreads();
    #pragma unroll
    for (int o = 128; o > 0; o >>= 1) {
        if (t < o) sh[t] += sh[t + o];
        __syncthreads();
    }
    if (t == 0) {
        float logit = sh[0] + bias[0];
        out[b] = 1.0f / (1.0f + expf(-logit));
    }
}

extern "C" void kernel_launch(void* const* d_in, const int* in_sizes, int n_in,
                              void* d_out, int out_size)
{
    const int*   queries = (const int*)d_in[0];
    const int*   docs    = (const int*)d_in[1];
    const float* emb     = (const float*)d_in[2];
    const float* W       = (const float*)d_in[3];
    const float* bias    = (const float*)d_in[4];
    float*       out     = (float*)d_out;

    knrm_zero<<<(B_ * QN * KN + 255) / 256, 256>>>();

    dim3 grid(SPLIT, B_);
    knrm_main<<<grid, TPB>>>(queries, docs, emb);

    knrm_epilogue<<<B_, 256>>>(W, bias, out);
}